// round 12
// baseline (speedup 1.0000x reference)
#include <cuda_runtime.h>
#include <cuda_bf16.h>
#include <cstdint>

// ---------------------------------------------------------------------------
// JointRetriveDeformHead — round 11
//  * k_pointnet widened to 512 threads / 16 warps (occ 12.5% -> 25%): each
//    warp owns one m16 A-tile (ahi 32 regs, d 16 regs) and produces 2 points
//    per chunk. Same total work, 2x independent warps per SMSP.
//  * Independent pre-kernels (transpose/preSC1/preP1) forked onto a
//    non-blocking stream, joined before k_fc (event fork/join, capture-safe).
//  * Rest = round-8 passing code.
// ---------------------------------------------------------------------------

#define B_      64
#define S_      1024
#define D_      256
#define KRET    10
#define NPART   16
#define NPAR    96
#define PSRC3   1536

__device__ float g_pool[2 * B_ * D_];
__device__ float g_ret [B_ * D_];
__device__ float g_T   [B_ * D_];
__device__ int   g_idx [B_ * KRET];
__device__ float g_par [B_ * KRET * NPAR];
__device__ float g_SC1 [S_ * D_];
__device__ float g_P1  [S_ * NPART * D_];
__device__ float g_varT[D_ * S_];
__device__ float g_rscT[D_ * S_];
__device__ unsigned short g_A3h[2 * 256 * 128];   // W3^T hi limb [enc][ch][k]
__device__ unsigned short g_A3l[2 * 256 * 128];   // W3^T lo limb

typedef unsigned long long u64;

__device__ __forceinline__ u64 pk(float lo, float hi) {
    u64 r; asm("mov.b64 %0,{%1,%2};" : "=l"(r) : "f"(lo), "f"(hi)); return r;
}
__device__ __forceinline__ void upk(u64 v, float& lo, float& hi) {
    asm("mov.b64 {%0,%1},%2;" : "=f"(lo), "=f"(hi) : "l"(v));
}
__device__ __forceinline__ u64 fma2(u64 a, u64 b, u64 c) {
    u64 d; asm("fma.rn.f32x2 %0,%1,%2,%3;" : "=l"(d) : "l"(a), "l"(b), "l"(c)); return d;
}
__device__ __forceinline__ void split_bf16(float v, unsigned short& h, unsigned short& l) {
    __nv_bfloat16 bh = __float2bfloat16(v);
    float fh = __bfloat162float(bh);
    __nv_bfloat16 bl = __float2bfloat16(v - fh);
    h = __bfloat16_as_ushort(bh);
    l = __bfloat16_as_ushort(bl);
}

#define MMA16816(d0,d1,d2,d3,a0,a1,a2,a3,b0,b1) \
    asm volatile("mma.sync.aligned.m16n8k16.row.col.f32.bf16.bf16.f32 " \
        "{%0,%1,%2,%3}, {%4,%5,%6,%7}, {%8,%9}, {%0,%1,%2,%3};" \
        : "+f"(d0),"+f"(d1),"+f"(d2),"+f"(d3) \
        : "r"(a0),"r"(a1),"r"(a2),"r"(a3),"r"(b0),"r"(b1))

// dynamic smem layout (bytes)
#define OFF_ALO 0          // u16 [256][136]       = 69632
#define OFF_BH  69632      // u16 [2][32][136]     = 17408
#define OFF_BL  87040      // u16 [2][32][136]     = 17408
#define OFF_H1W 104448     // float [16][64][2]    = 8192 (warp-private slices)
#define SMEMSZ  112640
#define BUFSZ   8704

// ---------------------------------------------------------------------------
// Prepack: W3^T bf16 limbs, [enc][ch][k] contiguous-k. grid 256, 256 thr.
// ---------------------------------------------------------------------------
__global__ __launch_bounds__(256)
void k_prepackA(const float* __restrict__ teW3, const float* __restrict__ reW3)
{
    int idx = blockIdx.x * 256 + threadIdx.x;   // 65536
    int enc = idx >> 15;
    int r   = idx & 32767;
    int ch  = r >> 7;
    int k   = r & 127;
    const float* W3 = enc ? reW3 : teW3;
    float w = W3[k * 256 + ch];
    unsigned short h, l;
    split_bf16(w, h, l);
    g_A3h[idx] = h;
    g_A3l[idx] = l;
}

// ---------------------------------------------------------------------------
// Kernel A: transpose var & rsc to [k][s]
// ---------------------------------------------------------------------------
__global__ __launch_bounds__(256)
void k_transpose(const float* __restrict__ var, const float* __restrict__ rsc)
{
    __shared__ float tv[32][33];
    __shared__ float tr[32][33];
    const int tx = threadIdx.x, ty = threadIdx.y;
    const int s0 = blockIdx.x * 32, k0 = blockIdx.y * 32;
    #pragma unroll
    for (int jj = 0; jj < 4; ++jj) {
        int s = s0 + ty + jj * 8;
        tv[ty + jj * 8][tx] = var[s * D_ + k0 + tx];
        tr[ty + jj * 8][tx] = rsc[s * D_ + k0 + tx];
    }
    __syncthreads();
    #pragma unroll
    for (int jj = 0; jj < 4; ++jj) {
        int k = k0 + ty + jj * 8;
        g_varT[k * S_ + s0 + tx] = tv[tx][ty + jj * 8];
        g_rscT[k * S_ + s0 + tx] = tr[tx][ty + jj * 8];
    }
}

// ---------------------------------------------------------------------------
// Kernel C: SC1 for 8 sources per block
// ---------------------------------------------------------------------------
__global__ __launch_bounds__(256, 3)
void k_preSC1(const float* __restrict__ src_codes,
              const float* __restrict__ decW1, const float* __restrict__ decb1)
{
    const int s0 = blockIdx.x * 8, t = threadIdx.x;
    __shared__ float scs[8][256];
    #pragma unroll
    for (int q = 0; q < 8; ++q)
        scs[q][t] = src_codes[(s0 + q) * 256 + t];
    __syncthreads();

    float acc[8];
    float bb = decb1[t];
    #pragma unroll
    for (int q = 0; q < 8; ++q) acc[q] = bb;
    #pragma unroll 4
    for (int i = 0; i < 256; ++i) {
        float w = decW1[(256 + i) * 256 + t];
        #pragma unroll
        for (int q = 0; q < 8; ++q)
            acc[q] = fmaf(scs[q][i], w, acc[q]);
    }
    #pragma unroll
    for (int q = 0; q < 8; ++q)
        g_SC1[(s0 + q) * 256 + t] = acc[q];
}

// ---------------------------------------------------------------------------
// Kernel D: P1[s][p] = part[s,p] . W1tail
// ---------------------------------------------------------------------------
__global__ __launch_bounds__(256, 4)
void k_preP1(const float* __restrict__ part_latent, const float* __restrict__ decW1)
{
    const int s = blockIdx.x, t = threadIdx.x;
    __shared__ float part[NPART][32];
    ((float*)part)[t]       = part_latent[s * (NPART * 32) + t];
    ((float*)part)[t + 256] = part_latent[s * (NPART * 32) + t + 256];
    __syncthreads();

    float wt[32];
    #pragma unroll
    for (int i = 0; i < 32; ++i)
        wt[i] = decW1[(512 + i) * 256 + t];
    #pragma unroll 2
    for (int p = 0; p < NPART; ++p) {
        float v = 0.f;
        #pragma unroll
        for (int i = 0; i < 32; ++i)
            v = fmaf(part[p][i], wt[i], v);
        g_P1[(s * NPART + p) * 256 + t] = v;
    }
}

// ---------------------------------------------------------------------------
// Kernel 1: PointNet. grid (64,2), 512 threads / 16 warps.
// Warp w owns channel rows [w*16, w*16+16) and produces points {w*2, w*2+1}.
// ---------------------------------------------------------------------------
__global__ __launch_bounds__(512, 1)
void k_pointnet(const float* __restrict__ noc,
                const float* __restrict__ teW1, const float* __restrict__ teb1,
                const float* __restrict__ teW2, const float* __restrict__ teb2,
                const float* __restrict__ teb3,
                const float* __restrict__ reW1, const float* __restrict__ reb1,
                const float* __restrict__ reW2, const float* __restrict__ reb2,
                const float* __restrict__ reb3)
{
    extern __shared__ char smem[];
    const int b = blockIdx.x;
    const int enc = blockIdx.y;
    const float* W1 = enc ? reW1 : teW1; const float* b1 = enc ? reb1 : teb1;
    const float* W2 = enc ? reW2 : teW2; const float* b2 = enc ? reb2 : teb2;
    const float* b3 = enc ? reb3 : teb3;

    const int t = threadIdx.x;
    const int warp = t >> 5, lane = t & 31;
    const int g = lane >> 2, j = lane & 3;

    unsigned short* ALO = (unsigned short*)(smem + OFF_ALO);
    const uint32_t* ALO32 = (const uint32_t*)ALO;
    float* H1W = (float*)(smem + OFF_H1W) + warp * 128;   // [64 k][2 pts]

    // ---- stage A-lo limb into padded smem (2 threads per 128-u16 row) ----
    {
        const uint4* src = (const uint4*)(g_A3l + enc * 32768);
        const int row = t >> 1, half = t & 1;
        #pragma unroll
        for (int i = 0; i < 8; ++i)
            *(uint4*)(ALO + row * 136 + half * 64 + i * 8) = src[row * 16 + half * 8 + i];
    }

    // ---- A-hi fragments -> registers (32 u32/thread, one m16 tile) ----
    uint32_t ahi[32];
    {
        const uint32_t* AH = (const uint32_t*)(g_A3h + enc * 32768); // [256][64]
        const int r0 = warp * 16 + g;
        #pragma unroll
        for (int ks = 0; ks < 8; ++ks) {
            const int fi = ks * 4;
            ahi[fi + 0] = AH[r0 * 64 + j + 8 * ks];
            ahi[fi + 1] = AH[(r0 + 8) * 64 + j + 8 * ks];
            ahi[fi + 2] = AH[r0 * 64 + j + 4 + 8 * ks];
            ahi[fi + 3] = AH[(r0 + 8) * 64 + j + 4 + 8 * ks];
        }
    }

    // ---- warp-local producer constants (2 channels H1, 4 channels H2) ----
    float w1x[2], w1y[2], w1z[2], b1v[2];
    #pragma unroll
    for (int cc = 0; cc < 2; ++cc) {
        int ch = lane * 2 + cc;
        w1x[cc] = W1[ch]; w1y[cc] = W1[64 + ch]; w1z[cc] = W1[128 + ch];
        b1v[cc] = b1[ch];
    }
    const int c0 = lane * 4;
    const float4 bb2 = *(const float4*)&b2[c0];
    const u64 bb2p[4] = { pk(bb2.x, bb2.x), pk(bb2.y, bb2.y),
                          pk(bb2.z, bb2.z), pk(bb2.w, bb2.w) };

    float dmax[2] = { -1e30f, -1e30f };   // row g, row g+8 of this warp's tile

    // ---- warp-local scalar producer: points {warp*2, warp*2+1} of chunk ----
    auto produce = [&](int chunk, int bi) {
        unsigned short* BHd = (unsigned short*)(smem + OFF_BH + bi * BUFSZ);
        unsigned short* BLd = (unsigned short*)(smem + OFF_BL + bi * BUFSZ);
        float myx = 0.f;
        if (lane < 6)
            myx = noc[b * 3072 + (lane >> 1) * 1024 + chunk * 32 + warp * 2 + (lane & 1)];
        float x0[2], x1[2], x2[2];
        #pragma unroll
        for (int pp = 0; pp < 2; ++pp) {
            x0[pp] = __shfl_sync(0xffffffffu, myx, pp);
            x1[pp] = __shfl_sync(0xffffffffu, myx, 2 + pp);
            x2[pp] = __shfl_sync(0xffffffffu, myx, 4 + pp);
        }
        // H1: 3 -> 64, 2 channels per lane, 2 points
        #pragma unroll
        for (int cc = 0; cc < 2; ++cc) {
            float2 v;
            v.x = fmaxf(fmaf(x0[0], w1x[cc], fmaf(x1[0], w1y[cc], fmaf(x2[0], w1z[cc], b1v[cc]))), 0.f);
            v.y = fmaxf(fmaf(x0[1], w1x[cc], fmaf(x1[1], w1y[cc], fmaf(x2[1], w1z[cc], b1v[cc]))), 0.f);
            *(float2*)&H1W[(lane * 2 + cc) * 2] = v;
        }
        __syncwarp();
        // H2: 64 -> 128 (fp32 exact), 4 channels per lane, 2 points (1 pair)
        u64 acc[4];
        #pragma unroll
        for (int jj = 0; jj < 4; ++jj) acc[jj] = bb2p[jj];
        #pragma unroll 8
        for (int k = 0; k < 64; ++k) {
            u64 x = *(const u64*)&H1W[k * 2];            // LDS.64 broadcast
            float4 w = *(const float4*)&W2[k * 128 + c0];
            acc[0] = fma2(x, pk(w.x, w.x), acc[0]);
            acc[1] = fma2(x, pk(w.y, w.y), acc[1]);
            acc[2] = fma2(x, pk(w.z, w.z), acc[2]);
            acc[3] = fma2(x, pk(w.w, w.w), acc[3]);
        }
        float vals[2][4];
        #pragma unroll
        for (int jj = 0; jj < 4; ++jj)
            upk(acc[jj], vals[0][jj], vals[1][jj]);
        #pragma unroll
        for (int p = 0; p < 2; ++p) {
            int n = warp * 2 + p;
            unsigned short h[4], l[4];
            #pragma unroll
            for (int jj = 0; jj < 4; ++jj)
                split_bf16(fmaxf(vals[p][jj], 0.f), h[jj], l[jj]);
            u64 hp = (u64)h[0] | ((u64)h[1] << 16) | ((u64)h[2] << 32) | ((u64)h[3] << 48);
            u64 lp = (u64)l[0] | ((u64)l[1] << 16) | ((u64)l[2] << 32) | ((u64)l[3] << 48);
            *(u64*)((char*)BHd + n * 272 + c0 * 2) = hp;
            *(u64*)((char*)BLd + n * 272 + c0 * 2) = lp;
        }
    };

    // prologue: fill buffer 0 with chunk 0
    produce(0, 0);
    __syncthreads();

    #pragma unroll 1
    for (int chunk = 0; chunk < 32; ++chunk) {
        const int cur = chunk & 1;
        const uint32_t* BH32 = (const uint32_t*)(smem + OFF_BH + cur * BUFSZ);
        const uint32_t* BL32 = (const uint32_t*)(smem + OFF_BL + cur * BUFSZ);

        // ---- phase 1: issue all MMAs for this chunk (tensor pipe) ----
        float d[4][4];
        #pragma unroll
        for (int nt = 0; nt < 4; ++nt)
            #pragma unroll
            for (int e = 0; e < 4; ++e) d[nt][e] = 0.f;

        #pragma unroll
        for (int ks = 0; ks < 8; ++ks) {
            uint32_t bh0[4], bh1[4], bl0[4], bl1[4];
            #pragma unroll
            for (int nt = 0; nt < 4; ++nt) {
                const uint32_t* BHrow = BH32 + (nt * 8 + g) * 68;
                const uint32_t* BLrow = BL32 + (nt * 8 + g) * 68;
                bh0[nt] = BHrow[j + 8 * ks];
                bh1[nt] = BHrow[j + 4 + 8 * ks];
                bl0[nt] = BLrow[j + 8 * ks];
                bl1[nt] = BLrow[j + 4 + 8 * ks];
            }
            const int fi = ks * 4;
            uint32_t a0 = ahi[fi], a1 = ahi[fi+1], a2 = ahi[fi+2], a3 = ahi[fi+3];
            #pragma unroll
            for (int nt = 0; nt < 4; ++nt) {
                MMA16816(d[nt][0], d[nt][1], d[nt][2], d[nt][3],
                         a0, a1, a2, a3, bh0[nt], bh1[nt]);
                MMA16816(d[nt][0], d[nt][1], d[nt][2], d[nt][3],
                         a0, a1, a2, a3, bl0[nt], bl1[nt]);
            }
            const int r0 = warp * 16 + g;
            uint32_t l0 = ALO32[r0 * 68 + j + 8 * ks];
            uint32_t l1 = ALO32[(r0 + 8) * 68 + j + 8 * ks];
            uint32_t l2 = ALO32[r0 * 68 + j + 4 + 8 * ks];
            uint32_t l3 = ALO32[(r0 + 8) * 68 + j + 4 + 8 * ks];
            #pragma unroll
            for (int nt = 0; nt < 4; ++nt)
                MMA16816(d[nt][0], d[nt][1], d[nt][2], d[nt][3],
                         l0, l1, l2, l3, bh0[nt], bh1[nt]);
        }

        // ---- phase 2: warp-local produce of next chunk (fma pipe) ----
        if (chunk < 31)
            produce(chunk + 1, cur ^ 1);

        // ---- phase 3: consume accumulators ----
        #pragma unroll
        for (int nt = 0; nt < 4; ++nt) {
            dmax[0] = fmaxf(dmax[0], fmaxf(d[nt][0], d[nt][1]));
            dmax[1] = fmaxf(dmax[1], fmaxf(d[nt][2], d[nt][3]));
        }
        __syncthreads();   // sole block-wide sync: B-buffer handoff
    }

    // reduce across the 4 threads sharing each channel row (j = 0..3)
    #pragma unroll
    for (int e = 0; e < 2; ++e) {
        dmax[e] = fmaxf(dmax[e], __shfl_xor_sync(0xffffffffu, dmax[e], 1));
        dmax[e] = fmaxf(dmax[e], __shfl_xor_sync(0xffffffffu, dmax[e], 2));
    }
    if (j == 0) {
        #pragma unroll
        for (int hf = 0; hf < 2; ++hf) {
            int ch = warp * 16 + hf * 8 + g;
            g_pool[(enc * B_ + b) * D_ + ch] = fmaxf(dmax[hf] + b3[ch], 0.f);
        }
    }
}

// ---------------------------------------------------------------------------
// Kernel 2: final fc + T = tgt @ dec_W1[0:256]
// ---------------------------------------------------------------------------
__global__ __launch_bounds__(256, 1)
void k_fc(const float* __restrict__ teWf, const float* __restrict__ tebf,
          const float* __restrict__ reWf, const float* __restrict__ rebf,
          const float* __restrict__ decW1)
{
    const int b = blockIdx.x, t = threadIdx.x;
    __shared__ float ste[256], sre[256], stgt[256];
    ste[t] = g_pool[b * D_ + t];
    sre[t] = g_pool[(B_ + b) * D_ + t];
    __syncthreads();

    float a = tebf[t], r = rebf[t];
    #pragma unroll 8
    for (int i = 0; i < 256; ++i) {
        a = fmaf(ste[i], teWf[i * 256 + t], a);
        r = fmaf(sre[i], reWf[i * 256 + t], r);
    }
    g_ret[b * D_ + t] = r;
    stgt[t] = a;
    __syncthreads();

    float tv = 0.f;
    #pragma unroll 8
    for (int i = 0; i < 256; ++i)
        tv = fmaf(stgt[i], decW1[i * 256 + t], tv);
    g_T[b * D_ + t] = tv;
}

// ---------------------------------------------------------------------------
// Kernel 3: distances + exact top-10
// ---------------------------------------------------------------------------
__global__ __launch_bounds__(256, 1)
void k_dist()
{
    const int b = blockIdx.x, t = threadIdx.x;
    __shared__ float rets[256];
    __shared__ float d[1024];
    __shared__ float sval[256];
    __shared__ int   sidx[256];

    rets[t] = g_ret[b * D_ + t];
    __syncthreads();

    const int s4 = 4 * t;
    float a0 = 0.f, a1 = 0.f, a2 = 0.f, a3 = 0.f;
    #pragma unroll 4
    for (int k = 0; k < 256; ++k) {
        float r = rets[k];
        float4 v = *(const float4*)&g_varT[k * S_ + s4];
        float4 c = *(const float4*)&g_rscT[k * S_ + s4];
        float d0 = r - c.x, d1 = r - c.y, d2 = r - c.z, d3 = r - c.w;
        a0 = fmaf(v.x, d0 * d0, a0);
        a1 = fmaf(v.y, d1 * d1, a1);
        a2 = fmaf(v.z, d2 * d2, a2);
        a3 = fmaf(v.w, d3 * d3, a3);
    }
    d[s4] = a0; d[s4 + 1] = a1; d[s4 + 2] = a2; d[s4 + 3] = a3;
    __syncthreads();

    for (int it = 0; it < KRET; ++it) {
        float bv = 1e30f; int bi = S_;
        #pragma unroll
        for (int q = 0; q < 4; ++q) {
            int s = q * 256 + t;
            float v = d[s];
            if (v < bv || (v == bv && s < bi)) { bv = v; bi = s; }
        }
        sval[t] = bv; sidx[t] = bi;
        __syncthreads();
        for (int off = 128; off > 0; off >>= 1) {
            if (t < off) {
                float v2 = sval[t + off]; int i2 = sidx[t + off];
                if (v2 < sval[t] || (v2 == sval[t] && i2 < sidx[t])) {
                    sval[t] = v2; sidx[t] = i2;
                }
            }
            __syncthreads();
        }
        if (t == 0) {
            g_idx[b * KRET + it] = sidx[0];
            d[sidx[0]] = 1e30f;
        }
        __syncthreads();
    }
}

// ---------------------------------------------------------------------------
// Kernel 4: decoder MLP -> params[96] per (b,k). 4 CTAs/SM.
// ---------------------------------------------------------------------------
__global__ __launch_bounds__(256, 4)
void k_decode_mlp(const float* __restrict__ decW2, const float* __restrict__ decb2,
                  const float* __restrict__ decW3, const float* __restrict__ decb3,
                  const float* __restrict__ proj,  const float* __restrict__ defp)
{
    const int bk = blockIdx.x;
    const int b = bk / KRET;
    const int t = threadIdx.x;
    const int s = g_idx[bk];

    __shared__ __align__(16) u64 H1p[256][10];
    __shared__ __align__(16) u64 H2p[256][10];
    __shared__ float raw[NPAR];

    {
        float base = g_T[b * D_ + t] + g_SC1[s * 256 + t];
        const float* p1 = &g_P1[s * (NPART * 256) + t];
        #pragma unroll
        for (int pr = 0; pr < 8; ++pr) {
            float lo = fmaxf(base + p1[(2 * pr) * 256], 0.f);
            float hi = fmaxf(base + p1[(2 * pr + 1) * 256], 0.f);
            H1p[t][pr] = pk(lo, hi);
        }
    }
    __syncthreads();

    const int c0 = (t & 63) * 4, pg = t >> 6;

    {
        u64 acc[2][4];
        float4 bb = *(const float4*)&decb2[c0];
        acc[0][0] = acc[1][0] = pk(bb.x, bb.x);
        acc[0][1] = acc[1][1] = pk(bb.y, bb.y);
        acc[0][2] = acc[1][2] = pk(bb.z, bb.z);
        acc[0][3] = acc[1][3] = pk(bb.w, bb.w);
        #pragma unroll 4
        for (int k = 0; k < 256; ++k) {
            ulonglong2 xx = *(const ulonglong2*)&H1p[k][pg * 2];
            float4 w = *(const float4*)&decW2[k * 256 + c0];
            u64 wp0 = pk(w.x, w.x), wp1 = pk(w.y, w.y);
            u64 wp2 = pk(w.z, w.z), wp3 = pk(w.w, w.w);
            acc[0][0] = fma2(xx.x, wp0, acc[0][0]);
            acc[0][1] = fma2(xx.x, wp1, acc[0][1]);
            acc[0][2] = fma2(xx.x, wp2, acc[0][2]);
            acc[0][3] = fma2(xx.x, wp3, acc[0][3]);
            acc[1][0] = fma2(xx.y, wp0, acc[1][0]);
            acc[1][1] = fma2(xx.y, wp1, acc[1][1]);
            acc[1][2] = fma2(xx.y, wp2, acc[1][2]);
            acc[1][3] = fma2(xx.y, wp3, acc[1][3]);
        }
        #pragma unroll
        for (int jj = 0; jj < 4; ++jj) {
            #pragma unroll
            for (int q = 0; q < 2; ++q) {
                float lo, hi; upk(acc[q][jj], lo, hi);
                lo = fmaxf(lo, 0.f); hi = fmaxf(hi, 0.f);
                H2p[c0 + jj][pg * 2 + q] = pk(lo, hi);
            }
        }
    }
    __syncthreads();

    const float* H2f = (const float*)H2p;
    if (t < NPAR) {
        const int p = t / 6, o = t % 6;
        float v = decb3[o];
        #pragma unroll 8
        for (int k = 0; k < 256; ++k)
            v = fmaf(H2f[k * 20 + p], decW3[k * 6 + o], v);
        raw[t] = v;
    }
    __syncthreads();

    if (t < NPAR) {
        float v = defp[s * NPAR + t];
        const float* pr = proj + (size_t)s * NPAR * NPAR + t * NPAR;
        #pragma unroll 8
        for (int jj = 0; jj < NPAR; ++jj)
            v = fmaf(pr[jj], raw[jj], v);
        g_par[bk * NPAR + t] = v;
    }
}

// ---------------------------------------------------------------------------
// Kernel 5: deformation pts = mat[s] @ params. grid (640, 6).
// ---------------------------------------------------------------------------
__global__ __launch_bounds__(256)
void k_deform(const float* __restrict__ mat, float* __restrict__ out)
{
    const int bk = blockIdx.x;
    const int t = threadIdx.x;
    const int s = g_idx[bk];
    __shared__ float par[NPAR];
    if (t < NPAR) par[t] = g_par[bk * NPAR + t];
    __syncthreads();

    const int r = blockIdx.y * 256 + t;
    const float* mr = mat + (size_t)s * PSRC3 * NPAR + (size_t)r * NPAR;
    float v = 0.f;
    #pragma unroll
    for (int j4 = 0; j4 < 24; ++j4) {
        float4 m4 = *(const float4*)&mr[j4 * 4];
        v = fmaf(m4.x, par[j4 * 4 + 0], v);
        v = fmaf(m4.y, par[j4 * 4 + 1], v);
        v = fmaf(m4.z, par[j4 * 4 + 2], v);
        v = fmaf(m4.w, par[j4 * 4 + 3], v);
    }
    out[(size_t)bk * PSRC3 + r] = v;
}

// ---------------------------------------------------------------------------
extern "C" void kernel_launch(void* const* d_in, const int* in_sizes, int n_in,
                              void* d_out, int out_size)
{
    const float* noc  = (const float*)d_in[0];
    const float* teW1 = (const float*)d_in[1];  const float* teb1 = (const float*)d_in[2];
    const float* teW2 = (const float*)d_in[3];  const float* teb2 = (const float*)d_in[4];
    const float* teW3 = (const float*)d_in[5];  const float* teb3 = (const float*)d_in[6];
    const float* teWf = (const float*)d_in[7];  const float* tebf = (const float*)d_in[8];
    const float* reW1 = (const float*)d_in[9];  const float* reb1 = (const float*)d_in[10];
    const float* reW2 = (const float*)d_in[11]; const float* reb2 = (const float*)d_in[12];
    const float* reW3 = (const float*)d_in[13]; const float* reb3 = (const float*)d_in[14];
    const float* reWf = (const float*)d_in[15]; const float* rebf = (const float*)d_in[16];
    const float* decW1 = (const float*)d_in[17]; const float* decb1 = (const float*)d_in[18];
    const float* decW2 = (const float*)d_in[19]; const float* decb2 = (const float*)d_in[20];
    const float* decW3 = (const float*)d_in[21]; const float* decb3 = (const float*)d_in[22];
    const float* ret_src = (const float*)d_in[23];
    const float* src_codes = (const float*)d_in[24];
    const float* src_var = (const float*)d_in[25];
    const float* part_latent = (const float*)d_in[26];
    const float* defp = (const float*)d_in[27];
    const float* proj = (const float*)d_in[28];
    const float* mat  = (const float*)d_in[29];
    float* out = (float*)d_out;

    static cudaStream_t s2 = nullptr;
    static cudaEvent_t evFork = nullptr, evJoin = nullptr;
    if (!s2) {
        cudaStreamCreateWithFlags(&s2, cudaStreamNonBlocking);
        cudaEventCreateWithFlags(&evFork, cudaEventDisableTiming);
        cudaEventCreateWithFlags(&evJoin, cudaEventDisableTiming);
    }

    cudaFuncSetAttribute(k_pointnet, cudaFuncAttributeMaxDynamicSharedMemorySize, SMEMSZ);

    // fork: independent pre-kernels on s2, pointnet path on main stream
    cudaEventRecord(evFork, 0);
    cudaStreamWaitEvent(s2, evFork, 0);

    dim3 gt(32, 8), bt(32, 8);
    k_transpose<<<gt, bt, 0, s2>>>(src_var, ret_src);
    k_preSC1<<<128, 256, 0, s2>>>(src_codes, decW1, decb1);
    k_preP1<<<S_, 256, 0, s2>>>(part_latent, decW1);

    k_prepackA<<<256, 256>>>(teW3, reW3);
    dim3 g1(B_, 2);
    k_pointnet<<<g1, 512, SMEMSZ>>>(noc,
                                    teW1, teb1, teW2, teb2, teb3,
                                    reW1, reb1, reW2, reb2, reb3);

    // join before consumers
    cudaEventRecord(evJoin, s2);
    cudaStreamWaitEvent(0, evJoin, 0);

    k_fc<<<B_, 256>>>(teWf, tebf, reWf, rebf, decW1);
    k_dist<<<B_, 256>>>();
    k_decode_mlp<<<B_ * KRET, 256>>>(decW2, decb2, decW3, decb3, proj, defp);
    dim3 g5(B_ * KRET, 6);
    k_deform<<<g5, 256>>>(mat, out);
}

// round 13
// speedup vs baseline: 1.1343x; 1.1343x over previous
#include <cuda_runtime.h>
#include <cuda_bf16.h>
#include <cstdint>

// ---------------------------------------------------------------------------
// JointRetriveDeformHead — round 12
//  * REVERT pointnet + launch structure to round-8 exact form (best: 392.5us).
//  * k_deform rewritten: smem-staged coalesced mat tiles (64 rows x 384B per
//    tile, float4 loads, pad-104 smem) + 4-threads/row dot + shfl reduce.
//    Kills the 32-wavefront-per-LDG L1tex pathology of the old row-per-thread
//    layout (6144 -> ~770 wavefronts per block).
// ---------------------------------------------------------------------------

#define B_      64
#define S_      1024
#define D_      256
#define KRET    10
#define NPART   16
#define NPAR    96
#define PSRC3   1536

__device__ float g_pool[2 * B_ * D_];
__device__ float g_ret [B_ * D_];
__device__ float g_T   [B_ * D_];
__device__ int   g_idx [B_ * KRET];
__device__ float g_par [B_ * KRET * NPAR];
__device__ float g_SC1 [S_ * D_];
__device__ float g_P1  [S_ * NPART * D_];
__device__ float g_varT[D_ * S_];
__device__ float g_rscT[D_ * S_];
__device__ unsigned short g_A3h[2 * 256 * 128];   // W3^T hi limb [enc][ch][k]
__device__ unsigned short g_A3l[2 * 256 * 128];   // W3^T lo limb

typedef unsigned long long u64;

__device__ __forceinline__ u64 pk(float lo, float hi) {
    u64 r; asm("mov.b64 %0,{%1,%2};" : "=l"(r) : "f"(lo), "f"(hi)); return r;
}
__device__ __forceinline__ void upk(u64 v, float& lo, float& hi) {
    asm("mov.b64 {%0,%1},%2;" : "=f"(lo), "=f"(hi) : "l"(v));
}
__device__ __forceinline__ u64 fma2(u64 a, u64 b, u64 c) {
    u64 d; asm("fma.rn.f32x2 %0,%1,%2,%3;" : "=l"(d) : "l"(a), "l"(b), "l"(c)); return d;
}
__device__ __forceinline__ void split_bf16(float v, unsigned short& h, unsigned short& l) {
    __nv_bfloat16 bh = __float2bfloat16(v);
    float fh = __bfloat162float(bh);
    __nv_bfloat16 bl = __float2bfloat16(v - fh);
    h = __bfloat16_as_ushort(bh);
    l = __bfloat16_as_ushort(bl);
}

#define MMA16816(d0,d1,d2,d3,a0,a1,a2,a3,b0,b1) \
    asm volatile("mma.sync.aligned.m16n8k16.row.col.f32.bf16.bf16.f32 " \
        "{%0,%1,%2,%3}, {%4,%5,%6,%7}, {%8,%9}, {%0,%1,%2,%3};" \
        : "+f"(d0),"+f"(d1),"+f"(d2),"+f"(d3) \
        : "r"(a0),"r"(a1),"r"(a2),"r"(a3),"r"(b0),"r"(b1))

// dynamic smem layout (bytes) — pointnet
#define OFF_ALO 0          // u16 [256][136]  = 69632
#define OFF_BH  69632      // u16 [32][136]   = 8704
#define OFF_BL  78336      // u16 [32][136]   = 8704
#define OFF_H1  87040      // float [64][36]  = 9216
#define OFF_X   96256      // float [3][32]   = 384
#define SMEMSZ  96640

// ---------------------------------------------------------------------------
// Prepack: W3^T bf16 limbs, [enc][ch][k] contiguous-k. grid 256, 256 thr.
// ---------------------------------------------------------------------------
__global__ __launch_bounds__(256)
void k_prepackA(const float* __restrict__ teW3, const float* __restrict__ reW3)
{
    int idx = blockIdx.x * 256 + threadIdx.x;   // 65536
    int enc = idx >> 15;
    int r   = idx & 32767;
    int ch  = r >> 7;
    int k   = r & 127;
    const float* W3 = enc ? reW3 : teW3;
    float w = W3[k * 256 + ch];
    unsigned short h, l;
    split_bf16(w, h, l);
    g_A3h[idx] = h;
    g_A3l[idx] = l;
}

// ---------------------------------------------------------------------------
// Kernel A: transpose var & rsc to [k][s]
// ---------------------------------------------------------------------------
__global__ __launch_bounds__(256)
void k_transpose(const float* __restrict__ var, const float* __restrict__ rsc)
{
    __shared__ float tv[32][33];
    __shared__ float tr[32][33];
    const int tx = threadIdx.x, ty = threadIdx.y;
    const int s0 = blockIdx.x * 32, k0 = blockIdx.y * 32;
    #pragma unroll
    for (int jj = 0; jj < 4; ++jj) {
        int s = s0 + ty + jj * 8;
        tv[ty + jj * 8][tx] = var[s * D_ + k0 + tx];
        tr[ty + jj * 8][tx] = rsc[s * D_ + k0 + tx];
    }
    __syncthreads();
    #pragma unroll
    for (int jj = 0; jj < 4; ++jj) {
        int k = k0 + ty + jj * 8;
        g_varT[k * S_ + s0 + tx] = tv[tx][ty + jj * 8];
        g_rscT[k * S_ + s0 + tx] = tr[tx][ty + jj * 8];
    }
}

// ---------------------------------------------------------------------------
// Kernel C: SC1 for 8 sources per block
// ---------------------------------------------------------------------------
__global__ __launch_bounds__(256, 3)
void k_preSC1(const float* __restrict__ src_codes,
              const float* __restrict__ decW1, const float* __restrict__ decb1)
{
    const int s0 = blockIdx.x * 8, t = threadIdx.x;
    __shared__ float scs[8][256];
    #pragma unroll
    for (int q = 0; q < 8; ++q)
        scs[q][t] = src_codes[(s0 + q) * 256 + t];
    __syncthreads();

    float acc[8];
    float bb = decb1[t];
    #pragma unroll
    for (int q = 0; q < 8; ++q) acc[q] = bb;
    #pragma unroll 4
    for (int i = 0; i < 256; ++i) {
        float w = decW1[(256 + i) * 256 + t];
        #pragma unroll
        for (int q = 0; q < 8; ++q)
            acc[q] = fmaf(scs[q][i], w, acc[q]);
    }
    #pragma unroll
    for (int q = 0; q < 8; ++q)
        g_SC1[(s0 + q) * 256 + t] = acc[q];
}

// ---------------------------------------------------------------------------
// Kernel D: P1[s][p] = part[s,p] . W1tail
// ---------------------------------------------------------------------------
__global__ __launch_bounds__(256, 4)
void k_preP1(const float* __restrict__ part_latent, const float* __restrict__ decW1)
{
    const int s = blockIdx.x, t = threadIdx.x;
    __shared__ float part[NPART][32];
    ((float*)part)[t]       = part_latent[s * (NPART * 32) + t];
    ((float*)part)[t + 256] = part_latent[s * (NPART * 32) + t + 256];
    __syncthreads();

    float wt[32];
    #pragma unroll
    for (int i = 0; i < 32; ++i)
        wt[i] = decW1[(512 + i) * 256 + t];
    #pragma unroll 2
    for (int p = 0; p < NPART; ++p) {
        float v = 0.f;
        #pragma unroll
        for (int i = 0; i < 32; ++i)
            v = fmaf(part[p][i], wt[i], v);
        g_P1[(s * NPART + p) * 256 + t] = v;
    }
}

// ---------------------------------------------------------------------------
// Kernel 1: PointNet (round-8 exact). grid (64,2), 256 threads, mma.sync H3.
// ---------------------------------------------------------------------------
__global__ __launch_bounds__(256, 1)
void k_pointnet(const float* __restrict__ noc,
                const float* __restrict__ teW1, const float* __restrict__ teb1,
                const float* __restrict__ teW2, const float* __restrict__ teb2,
                const float* __restrict__ teb3,
                const float* __restrict__ reW1, const float* __restrict__ reb1,
                const float* __restrict__ reW2, const float* __restrict__ reb2,
                const float* __restrict__ reb3)
{
    extern __shared__ char smem[];
    const int b = blockIdx.x;
    const int enc = blockIdx.y;
    const float* W1 = enc ? reW1 : teW1; const float* b1 = enc ? reb1 : teb1;
    const float* W2 = enc ? reW2 : teW2; const float* b2 = enc ? reb2 : teb2;
    const float* b3 = enc ? reb3 : teb3;

    const int t = threadIdx.x;
    const int warp = t >> 5, lane = t & 31;
    const int g = lane >> 2, j = lane & 3;

    unsigned short* ALO = (unsigned short*)(smem + OFF_ALO);
    unsigned short* BHs = (unsigned short*)(smem + OFF_BH);
    unsigned short* BLs = (unsigned short*)(smem + OFF_BL);
    float* H1c = (float*)(smem + OFF_H1);
    float* Xf  = (float*)(smem + OFF_X);
    const uint32_t* ALO32 = (const uint32_t*)ALO;
    const uint32_t* BH32  = (const uint32_t*)BHs;
    const uint32_t* BL32  = (const uint32_t*)BLs;

    {
        const uint4* src = (const uint4*)(g_A3l + enc * 32768);
        #pragma unroll
        for (int i = 0; i < 16; ++i)
            *(uint4*)(ALO + t * 136 + i * 8) = src[t * 16 + i];
    }

    uint32_t ahi[64];
    {
        const uint32_t* AH = (const uint32_t*)(g_A3h + enc * 32768); // [256][64]
        #pragma unroll
        for (int mt = 0; mt < 2; ++mt) {
            const int r0 = warp * 32 + mt * 16 + g;
            #pragma unroll
            for (int ks = 0; ks < 8; ++ks) {
                const int fi = (mt * 8 + ks) * 4;
                ahi[fi + 0] = AH[r0 * 64 + j + 8 * ks];
                ahi[fi + 1] = AH[(r0 + 8) * 64 + j + 8 * ks];
                ahi[fi + 2] = AH[r0 * 64 + j + 4 + 8 * ks];
                ahi[fi + 3] = AH[(r0 + 8) * 64 + j + 4 + 8 * ks];
            }
        }
    }

    const int colB = t & 63, pgB = t >> 6;
    const int c0C = (t & 31) * 4, pgC = t >> 5;
    const float w10 = W1[colB], w11 = W1[64 + colB], w12 = W1[128 + colB];
    const float bb1 = b1[colB];
    const float4 bb2 = *(const float4*)&b2[c0C];
    const u64 bb2p[4] = { pk(bb2.x, bb2.x), pk(bb2.y, bb2.y),
                          pk(bb2.z, bb2.z), pk(bb2.w, bb2.w) };

    float dmax[4] = { -1e30f, -1e30f, -1e30f, -1e30f };

    #pragma unroll 1
    for (int chunk = 0; chunk < 32; ++chunk) {
        __syncthreads();
        if (t < 96) {
            int c = t >> 5, p = t & 31;
            Xf[c * 32 + p] = noc[b * 3072 + c * 1024 + chunk * 32 + p];
        }
        __syncthreads();

        {
            float v[8];
            #pragma unroll
            for (int pp = 0; pp < 8; ++pp) {
                int p = pgB * 8 + pp;
                float h = fmaf(Xf[p], w10, fmaf(Xf[32 + p], w11, fmaf(Xf[64 + p], w12, bb1)));
                v[pp] = fmaxf(h, 0.f);
            }
            #pragma unroll
            for (int q = 0; q < 4; ++q)
                *(u64*)&H1c[colB * 36 + pgB * 8 + 2 * q] = pk(v[2*q], v[2*q+1]);
        }
        __syncthreads();

        {
            u64 acc[2][4];
            #pragma unroll
            for (int q = 0; q < 2; ++q)
                #pragma unroll
                for (int jj = 0; jj < 4; ++jj) acc[q][jj] = bb2p[jj];
            #pragma unroll 4
            for (int k = 0; k < 64; ++k) {
                ulonglong2 xa = *(const ulonglong2*)&H1c[k * 36 + pgC * 4];
                float4 w = *(const float4*)&W2[k * 128 + c0C];
                u64 wp0 = pk(w.x, w.x), wp1 = pk(w.y, w.y);
                u64 wp2 = pk(w.z, w.z), wp3 = pk(w.w, w.w);
                acc[0][0] = fma2(xa.x, wp0, acc[0][0]);
                acc[0][1] = fma2(xa.x, wp1, acc[0][1]);
                acc[0][2] = fma2(xa.x, wp2, acc[0][2]);
                acc[0][3] = fma2(xa.x, wp3, acc[0][3]);
                acc[1][0] = fma2(xa.y, wp0, acc[1][0]);
                acc[1][1] = fma2(xa.y, wp1, acc[1][1]);
                acc[1][2] = fma2(xa.y, wp2, acc[1][2]);
                acc[1][3] = fma2(xa.y, wp3, acc[1][3]);
            }
            float vals[4][4];
            #pragma unroll
            for (int q = 0; q < 2; ++q)
                #pragma unroll
                for (int jj = 0; jj < 4; ++jj)
                    upk(acc[q][jj], vals[2*q][jj], vals[2*q+1][jj]);
            #pragma unroll
            for (int p = 0; p < 4; ++p) {
                int n = pgC * 4 + p;
                unsigned short h[4], l[4];
                #pragma unroll
                for (int jj = 0; jj < 4; ++jj)
                    split_bf16(fmaxf(vals[p][jj], 0.f), h[jj], l[jj]);
                u64 hp = (u64)h[0] | ((u64)h[1] << 16) | ((u64)h[2] << 32) | ((u64)h[3] << 48);
                u64 lp = (u64)l[0] | ((u64)l[1] << 16) | ((u64)l[2] << 32) | ((u64)l[3] << 48);
                *(u64*)((char*)BHs + n * 272 + c0C * 2) = hp;
                *(u64*)((char*)BLs + n * 272 + c0C * 2) = lp;
            }
        }
        __syncthreads();

        float d[2][4][4];
        #pragma unroll
        for (int mt = 0; mt < 2; ++mt)
            #pragma unroll
            for (int nt = 0; nt < 4; ++nt)
                #pragma unroll
                for (int e = 0; e < 4; ++e) d[mt][nt][e] = 0.f;

        #pragma unroll
        for (int ks = 0; ks < 8; ++ks) {
            uint32_t bh0[4], bh1[4], bl0[4], bl1[4];
            #pragma unroll
            for (int nt = 0; nt < 4; ++nt) {
                const uint32_t* BHrow = BH32 + (nt * 8 + g) * 68;
                const uint32_t* BLrow = BL32 + (nt * 8 + g) * 68;
                bh0[nt] = BHrow[j + 8 * ks];
                bh1[nt] = BHrow[j + 4 + 8 * ks];
                bl0[nt] = BLrow[j + 8 * ks];
                bl1[nt] = BLrow[j + 4 + 8 * ks];
            }
            #pragma unroll
            for (int mt = 0; mt < 2; ++mt) {
                const int fi = (mt * 8 + ks) * 4;
                uint32_t a0 = ahi[fi], a1 = ahi[fi+1], a2 = ahi[fi+2], a3 = ahi[fi+3];
                #pragma unroll
                for (int nt = 0; nt < 4; ++nt) {
                    MMA16816(d[mt][nt][0], d[mt][nt][1], d[mt][nt][2], d[mt][nt][3],
                             a0, a1, a2, a3, bh0[nt], bh1[nt]);
                    MMA16816(d[mt][nt][0], d[mt][nt][1], d[mt][nt][2], d[mt][nt][3],
                             a0, a1, a2, a3, bl0[nt], bl1[nt]);
                }
                const int r0 = warp * 32 + mt * 16 + g;
                uint32_t l0 = ALO32[r0 * 68 + j + 8 * ks];
                uint32_t l1 = ALO32[(r0 + 8) * 68 + j + 8 * ks];
                uint32_t l2 = ALO32[r0 * 68 + j + 4 + 8 * ks];
                uint32_t l3 = ALO32[(r0 + 8) * 68 + j + 4 + 8 * ks];
                #pragma unroll
                for (int nt = 0; nt < 4; ++nt)
                    MMA16816(d[mt][nt][0], d[mt][nt][1], d[mt][nt][2], d[mt][nt][3],
                             l0, l1, l2, l3, bh0[nt], bh1[nt]);
            }
        }

        #pragma unroll
        for (int mt = 0; mt < 2; ++mt)
            #pragma unroll
            for (int nt = 0; nt < 4; ++nt) {
                dmax[mt*2+0] = fmaxf(dmax[mt*2+0], fmaxf(d[mt][nt][0], d[mt][nt][1]));
                dmax[mt*2+1] = fmaxf(dmax[mt*2+1], fmaxf(d[mt][nt][2], d[mt][nt][3]));
            }
    }

    #pragma unroll
    for (int e = 0; e < 4; ++e) {
        dmax[e] = fmaxf(dmax[e], __shfl_xor_sync(0xffffffffu, dmax[e], 1));
        dmax[e] = fmaxf(dmax[e], __shfl_xor_sync(0xffffffffu, dmax[e], 2));
    }
    if (j == 0) {
        #pragma unroll
        for (int mt = 0; mt < 2; ++mt)
            #pragma unroll
            for (int hf = 0; hf < 2; ++hf) {
                int ch = warp * 32 + mt * 16 + hf * 8 + g;
                g_pool[(enc * B_ + b) * D_ + ch] = fmaxf(dmax[mt*2+hf] + b3[ch], 0.f);
            }
    }
}

// ---------------------------------------------------------------------------
// Kernel 2: final fc + T = tgt @ dec_W1[0:256]
// ---------------------------------------------------------------------------
__global__ __launch_bounds__(256, 1)
void k_fc(const float* __restrict__ teWf, const float* __restrict__ tebf,
          const float* __restrict__ reWf, const float* __restrict__ rebf,
          const float* __restrict__ decW1)
{
    const int b = blockIdx.x, t = threadIdx.x;
    __shared__ float ste[256], sre[256], stgt[256];
    ste[t] = g_pool[b * D_ + t];
    sre[t] = g_pool[(B_ + b) * D_ + t];
    __syncthreads();

    float a = tebf[t], r = rebf[t];
    #pragma unroll 8
    for (int i = 0; i < 256; ++i) {
        a = fmaf(ste[i], teWf[i * 256 + t], a);
        r = fmaf(sre[i], reWf[i * 256 + t], r);
    }
    g_ret[b * D_ + t] = r;
    stgt[t] = a;
    __syncthreads();

    float tv = 0.f;
    #pragma unroll 8
    for (int i = 0; i < 256; ++i)
        tv = fmaf(stgt[i], decW1[i * 256 + t], tv);
    g_T[b * D_ + t] = tv;
}

// ---------------------------------------------------------------------------
// Kernel 3: distances + exact top-10
// ---------------------------------------------------------------------------
__global__ __launch_bounds__(256, 1)
void k_dist()
{
    const int b = blockIdx.x, t = threadIdx.x;
    __shared__ float rets[256];
    __shared__ float d[1024];
    __shared__ float sval[256];
    __shared__ int   sidx[256];

    rets[t] = g_ret[b * D_ + t];
    __syncthreads();

    const int s4 = 4 * t;
    float a0 = 0.f, a1 = 0.f, a2 = 0.f, a3 = 0.f;
    #pragma unroll 4
    for (int k = 0; k < 256; ++k) {
        float r = rets[k];
        float4 v = *(const float4*)&g_varT[k * S_ + s4];
        float4 c = *(const float4*)&g_rscT[k * S_ + s4];
        float d0 = r - c.x, d1 = r - c.y, d2 = r - c.z, d3 = r - c.w;
        a0 = fmaf(v.x, d0 * d0, a0);
        a1 = fmaf(v.y, d1 * d1, a1);
        a2 = fmaf(v.z, d2 * d2, a2);
        a3 = fmaf(v.w, d3 * d3, a3);
    }
    d[s4] = a0; d[s4 + 1] = a1; d[s4 + 2] = a2; d[s4 + 3] = a3;
    __syncthreads();

    for (int it = 0; it < KRET; ++it) {
        float bv = 1e30f; int bi = S_;
        #pragma unroll
        for (int q = 0; q < 4; ++q) {
            int s = q * 256 + t;
            float v = d[s];
            if (v < bv || (v == bv && s < bi)) { bv = v; bi = s; }
        }
        sval[t] = bv; sidx[t] = bi;
        __syncthreads();
        for (int off = 128; off > 0; off >>= 1) {
            if (t < off) {
                float v2 = sval[t + off]; int i2 = sidx[t + off];
                if (v2 < sval[t] || (v2 == sval[t] && i2 < sidx[t])) {
                    sval[t] = v2; sidx[t] = i2;
                }
            }
            __syncthreads();
        }
        if (t == 0) {
            g_idx[b * KRET + it] = sidx[0];
            d[sidx[0]] = 1e30f;
        }
        __syncthreads();
    }
}

// ---------------------------------------------------------------------------
// Kernel 4: decoder MLP -> params[96] per (b,k). 4 CTAs/SM.
// ---------------------------------------------------------------------------
__global__ __launch_bounds__(256, 4)
void k_decode_mlp(const float* __restrict__ decW2, const float* __restrict__ decb2,
                  const float* __restrict__ decW3, const float* __restrict__ decb3,
                  const float* __restrict__ proj,  const float* __restrict__ defp)
{
    const int bk = blockIdx.x;
    const int b = bk / KRET;
    const int t = threadIdx.x;
    const int s = g_idx[bk];

    __shared__ __align__(16) u64 H1p[256][10];
    __shared__ __align__(16) u64 H2p[256][10];
    __shared__ float raw[NPAR];

    {
        float base = g_T[b * D_ + t] + g_SC1[s * 256 + t];
        const float* p1 = &g_P1[s * (NPART * 256) + t];
        #pragma unroll
        for (int pr = 0; pr < 8; ++pr) {
            float lo = fmaxf(base + p1[(2 * pr) * 256], 0.f);
            float hi = fmaxf(base + p1[(2 * pr + 1) * 256], 0.f);
            H1p[t][pr] = pk(lo, hi);
        }
    }
    __syncthreads();

    const int c0 = (t & 63) * 4, pg = t >> 6;

    {
        u64 acc[2][4];
        float4 bb = *(const float4*)&decb2[c0];
        acc[0][0] = acc[1][0] = pk(bb.x, bb.x);
        acc[0][1] = acc[1][1] = pk(bb.y, bb.y);
        acc[0][2] = acc[1][2] = pk(bb.z, bb.z);
        acc[0][3] = acc[1][3] = pk(bb.w, bb.w);
        #pragma unroll 4
        for (int k = 0; k < 256; ++k) {
            ulonglong2 xx = *(const ulonglong2*)&H1p[k][pg * 2];
            float4 w = *(const float4*)&decW2[k * 256 + c0];
            u64 wp0 = pk(w.x, w.x), wp1 = pk(w.y, w.y);
            u64 wp2 = pk(w.z, w.z), wp3 = pk(w.w, w.w);
            acc[0][0] = fma2(xx.x, wp0, acc[0][0]);
            acc[0][1] = fma2(xx.x, wp1, acc[0][1]);
            acc[0][2] = fma2(xx.x, wp2, acc[0][2]);
            acc[0][3] = fma2(xx.x, wp3, acc[0][3]);
            acc[1][0] = fma2(xx.y, wp0, acc[1][0]);
            acc[1][1] = fma2(xx.y, wp1, acc[1][1]);
            acc[1][2] = fma2(xx.y, wp2, acc[1][2]);
            acc[1][3] = fma2(xx.y, wp3, acc[1][3]);
        }
        #pragma unroll
        for (int jj = 0; jj < 4; ++jj) {
            #pragma unroll
            for (int q = 0; q < 2; ++q) {
                float lo, hi; upk(acc[q][jj], lo, hi);
                lo = fmaxf(lo, 0.f); hi = fmaxf(hi, 0.f);
                H2p[c0 + jj][pg * 2 + q] = pk(lo, hi);
            }
        }
    }
    __syncthreads();

    const float* H2f = (const float*)H2p;
    if (t < NPAR) {
        const int p = t / 6, o = t % 6;
        float v = decb3[o];
        #pragma unroll 8
        for (int k = 0; k < 256; ++k)
            v = fmaf(H2f[k * 20 + p], decW3[k * 6 + o], v);
        raw[t] = v;
    }
    __syncthreads();

    if (t < NPAR) {
        float v = defp[s * NPAR + t];
        const float* pr = proj + (size_t)s * NPAR * NPAR + t * NPAR;
        #pragma unroll 8
        for (int jj = 0; jj < NPAR; ++jj)
            v = fmaf(pr[jj], raw[jj], v);
        g_par[bk * NPAR + t] = v;
    }
}

// ---------------------------------------------------------------------------
// Kernel 5: deformation pts = mat[s] @ params. grid (640, 6), smem-staged.
// Each block: 256 rows in 4 tiles of 64. Coalesced float4 tile loads into
// padded smem (stride 104 floats), 4 threads per row dot, 2-shfl reduce.
// ---------------------------------------------------------------------------
__global__ __launch_bounds__(256)
void k_deform(const float* __restrict__ mat, float* __restrict__ out)
{
    const int bk = blockIdx.x;
    const int t = threadIdx.x;
    const int s = g_idx[bk];
    __shared__ float par[NPAR];
    __shared__ __align__(16) float tilebuf[64 * 104];
    if (t < NPAR) par[t] = g_par[bk * NPAR + t];

    const float* mb = mat + (size_t)s * PSRC3 * NPAR;
    float* ob = out + (size_t)bk * PSRC3;
    const int row = t >> 2, q = t & 3;
    const int lane = t & 31;

    #pragma unroll 1
    for (int tile = 0; tile < 4; ++tile) {
        const int R0 = blockIdx.y * 256 + tile * 64;
        __syncthreads();   // prior tile reads done (and par ready on tile 0)
        // coalesced load: 64 rows x 24 float4 = 1536 float4
        const float4* src = (const float4*)(mb + (size_t)R0 * NPAR);
        #pragma unroll
        for (int i = 0; i < 6; ++i) {
            int idx = i * 256 + t;
            int r = idx / 24, c = idx % 24;
            *(float4*)&tilebuf[r * 104 + c * 4] = src[idx];
        }
        __syncthreads();
        // dot: thread (row, q) covers cols [q*24, q*24+24)
        float v = 0.f;
        const float* tb = &tilebuf[row * 104 + q * 24];
        const float* pq = &par[q * 24];
        #pragma unroll
        for (int i4 = 0; i4 < 6; ++i4) {
            float4 m4 = *(const float4*)&tb[i4 * 4];
            v = fmaf(m4.x, pq[i4 * 4 + 0], v);
            v = fmaf(m4.y, pq[i4 * 4 + 1], v);
            v = fmaf(m4.z, pq[i4 * 4 + 2], v);
            v = fmaf(m4.w, pq[i4 * 4 + 3], v);
        }
        v += __shfl_xor_sync(0xffffffffu, v, 1);
        v += __shfl_xor_sync(0xffffffffu, v, 2);
        if (q == 0)
            ob[R0 + row] = v;
        (void)lane;
    }
}

// ---------------------------------------------------------------------------
extern "C" void kernel_launch(void* const* d_in, const int* in_sizes, int n_in,
                              void* d_out, int out_size)
{
    const float* noc  = (const float*)d_in[0];
    const float* teW1 = (const float*)d_in[1];  const float* teb1 = (const float*)d_in[2];
    const float* teW2 = (const float*)d_in[3];  const float* teb2 = (const float*)d_in[4];
    const float* teW3 = (const float*)d_in[5];  const float* teb3 = (const float*)d_in[6];
    const float* teWf = (const float*)d_in[7];  const float* tebf = (const float*)d_in[8];
    const float* reW1 = (const float*)d_in[9];  const float* reb1 = (const float*)d_in[10];
    const float* reW2 = (const float*)d_in[11]; const float* reb2 = (const float*)d_in[12];
    const float* reW3 = (const float*)d_in[13]; const float* reb3 = (const float*)d_in[14];
    const float* reWf = (const float*)d_in[15]; const float* rebf = (const float*)d_in[16];
    const float* decW1 = (const float*)d_in[17]; const float* decb1 = (const float*)d_in[18];
    const float* decW2 = (const float*)d_in[19]; const float* decb2 = (const float*)d_in[20];
    const float* decW3 = (const float*)d_in[21]; const float* decb3 = (const float*)d_in[22];
    const float* ret_src = (const float*)d_in[23];
    const float* src_codes = (const float*)d_in[24];
    const float* src_var = (const float*)d_in[25];
    const float* part_latent = (const float*)d_in[26];
    const float* defp = (const float*)d_in[27];
    const float* proj = (const float*)d_in[28];
    const float* mat  = (const float*)d_in[29];
    float* out = (float*)d_out;

    cudaFuncSetAttribute(k_pointnet, cudaFuncAttributeMaxDynamicSharedMemorySize, SMEMSZ);

    dim3 gt(32, 8), bt(32, 8);
    k_transpose<<<gt, bt>>>(src_var, ret_src);
    k_prepackA<<<256, 256>>>(teW3, reW3);
    k_preSC1<<<128, 256>>>(src_codes, decW1, decb1);
    dim3 g1(B_, 2);
    k_pointnet<<<g1, 256, SMEMSZ>>>(noc,
                                    teW1, teb1, teW2, teb2, teb3,
                                    reW1, reb1, reW2, reb2, reb3);
    k_preP1<<<S_, 256>>>(part_latent, decW1);
    k_fc<<<B_, 256>>>(teWf, tebf, reWf, rebf, decW1);
    k_dist<<<B_, 256>>>();
    k_decode_mlp<<<B_ * KRET, 256>>>(decW2, decb2, decW3, decb3, proj, defp);
    dim3 g5(B_ * KRET, 6);
    k_deform<<<g5, 256>>>(mat, out);
}